// round 10
// baseline (speedup 1.0000x reference)
#include <cuda_runtime.h>

// R9: lane=(token,dim-quarter) decomposition. Dot/zs/dist/argmin/z are
// bit-exact reproductions of the R8-passing arithmetic (same leaf chains,
// same balanced reduction trees, same fp32 grid emulation). Codebook in
// padded SMEM (broadcast LDS) instead of registers -> 12 warps/SM.

constexpr int TOK   = 32768;        // B*N
constexpr int D     = 1024;
constexpr int S     = 4;
constexpr int ZSIZE = TOK * D;
constexpr int IDOFF = ZSIZE;
constexpr int VQOFF = ZSIZE + TOK;
constexpr int NBLK  = 512;          // 64 tokens per block
constexpr int CBP   = 272;          // padded code row: 4 quarters * 68
constexpr unsigned long long NEG2 = 0x8000000080000000ULL;

#define FULL 0xFFFFFFFFu

__device__ float g_partials[NBLK];

static __device__ __forceinline__ unsigned long long pk2(float x, float y) {
    unsigned long long r;
    asm("mov.b64 %0, {%1, %2};" : "=l"(r) : "f"(x), "f"(y));
    return r;
}
static __device__ __forceinline__ void upk2(unsigned long long v, float& x, float& y) {
    asm("mov.b64 {%0, %1}, %2;" : "=f"(x), "=f"(y) : "l"(v));
}
static __device__ __forceinline__ unsigned long long ffma2(
    unsigned long long a, unsigned long long b, unsigned long long c) {
    unsigned long long d;
    asm("fma.rn.f32x2 %0, %1, %2, %3;" : "=l"(d) : "l"(a), "l"(b), "l"(c));
    return d;
}
static __device__ __forceinline__ unsigned long long add2(
    unsigned long long a, unsigned long long b) {
    unsigned long long d;
    asm("add.rn.f32x2 %0, %1, %2;" : "=l"(d) : "l"(a), "l"(b));
    return d;
}

__global__ __launch_bounds__(128, 3) void dvq_kernel(
    const float* __restrict__ h, const float* __restrict__ cb,
    float* __restrict__ out)
{
    __shared__ float cb_pad[16 * CBP];   // [k][q][68] bank-padded
    __shared__ float csq_sm[16];
    __shared__ float red_sm[4];

    const int tid = threadIdx.x;
    const int w   = tid >> 5;
    const int L   = tid & 31;
    const int q   = L >> 3;              // dim quarter (64 dims)
    const int tl  = L & 7;               // token-in-group
    const int tok0 = blockIdx.x * 64;

    float errAcc = 0.0f;
    int idacc0 = 0, idacc1 = 0;

    for (int s = 0; s < S; s++) {
        __syncthreads();   // previous s's cb_pad consumers done
        // stage codebook for subspace s into padded layout
        for (int i = tid; i < 4096; i += 128) {
            int k = i >> 8, d = i & 255;
            cb_pad[k * CBP + (d >> 6) * 68 + (d & 63)] = cb[s * 4096 + i];
        }
        // csq: serial fp64 chain, ascending d (identical to R8's values)
        if (tid < 16) {
            const float* c = cb + s * 4096 + tid * 256;
            double a = 0.0;
            for (int d = 0; d < 256; d++) a = fma((double)c[d], (double)c[d], a);
            csq_sm[tid] = (float)a;
        }
        __syncthreads();

        #pragma unroll
        for (int gi = 0; gi < 2; gi++) {
            const int tok = tok0 + (w + gi * 4) * 8 + tl;
            const float4* hp = (const float4*)(h + (size_t)tok * D + s * 256 + q * 64);

            // load my 64 dims (16 x LDG.128, batched for MLP)
            float4 ZE[16];
            #pragma unroll
            for (int c = 0; c < 16; c++) ZE[c] = __ldcs(hp + c);
            unsigned long long ze2[32];
            #pragma unroll
            for (int c = 0; c < 16; c++) {
                ze2[2 * c]     = pk2(ZE[c].x, ZE[c].y);
                ze2[2 * c + 1] = pk2(ZE[c].z, ZE[c].w);
            }

            // ||ze||^2: leaf chains (== R8 per-lane chain) + R8's descending
            // tree: (l,l+16),(l,l+8) cross-lane, then 4,2,1 in-lane.
            float lz[8];
            #pragma unroll
            for (int j = 0; j < 8; j++) {
                unsigned long long a = 0ull;
                #pragma unroll
                for (int p = 0; p < 4; p++) a = ffma2(ze2[4 * j + p], ze2[4 * j + p], a);
                float x, y; upk2(a, x, y);
                lz[j] = x + y;
            }
            #pragma unroll
            for (int j = 0; j < 8; j++) lz[j] += __shfl_xor_sync(FULL, lz[j], 16);
            #pragma unroll
            for (int j = 0; j < 8; j++) lz[j] += __shfl_xor_sync(FULL, lz[j], 8);
            float za4[4], za2[2];
            #pragma unroll
            for (int j = 0; j < 4; j++) za4[j] = lz[j] + lz[j + 4];
            za2[0] = za4[0] + za4[2]; za2[1] = za4[1] + za4[3];
            const float zs = za2[0] + za2[1];

            // dots for 16 codes: leaf chains + R8's ascending tree
            // (in-lane = masks 1,2,4; cross-lane = masks 8,16)
            float v[16];
            #pragma unroll
            for (int k = 0; k < 16; k++) {
                const float* cptr = cb_pad + k * CBP + q * 68;
                float lv[8];
                #pragma unroll
                for (int j = 0; j < 8; j++) {
                    float4 c0 = *(const float4*)(cptr + j * 8);
                    float4 c1 = *(const float4*)(cptr + j * 8 + 4);
                    unsigned long long a = 0ull;
                    a = ffma2(ze2[4 * j + 0], pk2(c0.x, c0.y), a);
                    a = ffma2(ze2[4 * j + 1], pk2(c0.z, c0.w), a);
                    a = ffma2(ze2[4 * j + 2], pk2(c1.x, c1.y), a);
                    a = ffma2(ze2[4 * j + 3], pk2(c1.z, c1.w), a);
                    float x, y; upk2(a, x, y);
                    lv[j] = x + y;
                }
                float u0 = lv[0] + lv[1], u1 = lv[2] + lv[3];
                float u2 = lv[4] + lv[5], u3 = lv[6] + lv[7];
                float w0 = u0 + u1, w1 = u2 + u3;
                v[k] = w0 + w1;
            }
            #pragma unroll
            for (int k = 0; k < 16; k++) v[k] += __shfl_xor_sync(FULL, v[k], 8);
            #pragma unroll
            for (int k = 0; k < 16; k++) v[k] += __shfl_xor_sync(FULL, v[k], 16);

            // fp32 grid emulation of ref distance + first-min argmin
            float best = __fsub_rn(__fadd_rn(zs, csq_sm[0]), 2.0f * v[0]);
            int kb = 0;
            #pragma unroll
            for (int k = 1; k < 16; k++) {
                float dk = __fsub_rn(__fadd_rn(zs, csq_sm[k]), 2.0f * v[k]);
                if (dk < best) { best = dk; kb = k; }
            }

            // z = fl(ze + fl(zq - ze)) (exact, packed); loss accumulate
            const float* zq = cb_pad + kb * CBP + q * 68;
            float4* zo = (float4*)(out + (size_t)tok * D + s * 256 + q * 64);
            unsigned long long e2 = 0ull;
            #pragma unroll
            for (int c = 0; c < 16; c++) {
                float4 qv = *(const float4*)(zq + c * 4);
                unsigned long long q0 = pk2(qv.x, qv.y), q1 = pk2(qv.z, qv.w);
                unsigned long long d0 = add2(q0, ze2[2 * c] ^ NEG2);      // fl(zq-ze)
                unsigned long long d1 = add2(q1, ze2[2 * c + 1] ^ NEG2);
                unsigned long long z0 = add2(ze2[2 * c], d0);             // fl(ze+d)
                unsigned long long z1 = add2(ze2[2 * c + 1], d1);
                e2 = ffma2(d0, d0, e2);
                e2 = ffma2(d1, d1, e2);
                float4 ov;
                upk2(z0, ov.x, ov.y); upk2(z1, ov.z, ov.w);
                __stcs(zo + c, ov);
            }
            float ex, ey; upk2(e2, ex, ey);
            errAcc += ex + ey;

            if (q == 0) {
                if (gi == 0) idacc0 += kb << (4 * s);
                else         idacc1 += kb << (4 * s);
            }
        }
    }

    // ids (q==0 lanes hold them; tokens contiguous per warp-group)
    if (q == 0) {
        out[IDOFF + tok0 + (w + 0) * 8 + tl] = (float)idacc0;
        out[IDOFF + tok0 + (w + 4) * 8 + tl] = (float)idacc1;
    }

    // block loss partial
    #pragma unroll
    for (int m = 16; m >= 1; m >>= 1) errAcc += __shfl_xor_sync(FULL, errAcc, m);
    if (L == 0) red_sm[w] = errAcc;
    __syncthreads();
    if (tid == 0)
        g_partials[blockIdx.x] = (red_sm[0] + red_sm[1]) + (red_sm[2] + red_sm[3]);
}

__global__ __launch_bounds__(256) void dvq_fin_kernel(float* __restrict__ out) {
    __shared__ float red[256];
    float a = 0.0f;
    for (int j = threadIdx.x; j < NBLK; j += 256) a += g_partials[j];
    red[threadIdx.x] = a;
    __syncthreads();
    for (int st = 128; st > 0; st >>= 1) {
        if (threadIdx.x < st) red[threadIdx.x] += red[threadIdx.x + st];
        __syncthreads();
    }
    // vq_total = (1 + BETA) * sum_sq / (B*N*d); BETA=0.25, B*N*d = 8388608
    if (threadIdx.x == 0) out[VQOFF] = red[0] * (1.25f / 8388608.0f);
}

extern "C" void kernel_launch(void* const* d_in, const int* in_sizes, int n_in,
                              void* d_out, int out_size) {
    const float* h  = (const float*)d_in[0];
    const float* cb = (const float*)d_in[1];
    float* out = (float*)d_out;

    dvq_kernel<<<NBLK, 128>>>(h, cb, out);
    dvq_fin_kernel<<<1, 256>>>(out);
}